// round 16
// baseline (speedup 1.0000x reference)
#include <cuda_runtime.h>
#include <cuda_fp16.h>
#include <cstdint>
#include <math.h>

// ---------------- problem constants ----------------
#define BB 512
#define HH 512
#define EE 300
#define LCC 100
#define OO 2004
#define ANNOT_K 51200
#define NSPLIT 68          // 64 annot + 4 head splits
#define AHEAD_K 1324
#define MINP_LD 1840       // fp16 minp row: [h_new|c_t|ans|emb|pad4]
#define WIH_LD  1328       // 1324 padded

// ---------------- fp32 scratch ----------------
#define OFF_PART   0UL                   // 512*6800
#define OFF_ATTNW  3481600UL             // 512*100
#define OFF_GIS    3532800UL             // 512*1536 (gi static part)
#define OFF_GICP   4319232UL             // 2*512*1536 (gi c_t partials)
#define OFF_GH     5892096UL             // 512*1536
#define OFF_ETP    6678528UL             // 8*512*512
#define OFF_OLOGP  8775680UL             // 2*512*2004
#define OFF_Z1P    10827776UL            // 4*512*1024
#define OFF_Z2P    12924928UL            // 4*512*512
#define OFF_AHEAD  13973504UL            // 512*1324
#define F32_TOTAL  14651392UL

// ---------------- fp16 scratch ----------------
#define HOFF_ANNOT 0UL                   // 512*51200 (GEMM side-output)
#define HOFF_WIH   26214400UL            // 1536*1328
#define HOFF_MLPW  28254208UL            // 512*1840
#define HOFF_OUTW  29196288UL            // 2004*512
#define HOFF_Z1W   30222336UL            // 1024*1840
#define HOFF_Z2W   32106496UL            // 512*1024
#define HOFF_MINP  32630784UL            // 512*1840
#define HOFF_ET    33572864UL            // 512*512
#define HOFF_Z1    33835008UL            // 512*1024
#define F16_TOTAL  34359296UL

__device__ float g_f32[F32_TOTAL];
__device__ __align__(16) __half g_f16[F16_TOTAL];

// ---------------- grid barrier state ----------------
__device__ unsigned g_cnt = 0;
__device__ unsigned g_gen = 0;

__device__ __forceinline__ void gridbar() {
    __syncthreads();
    if (threadIdx.x == 0) {
        unsigned g = *(volatile unsigned*)&g_gen;
        __threadfence();
        if (atomicAdd(&g_cnt, 1) == gridDim.x - 1) {
            g_cnt = 0;
            __threadfence();
            atomicAdd(&g_gen, 1);
        } else {
            while (*(volatile unsigned*)&g_gen == g) __nanosleep(64);
        }
        __threadfence();
    }
    __syncthreads();
}

// ---------------- low-level helpers ----------------
__device__ __forceinline__ uint32_t smem_u32(const void* p) {
    uint32_t a;
    asm("{ .reg .u64 t; cvta.to.shared.u64 t, %1; cvt.u32.u64 %0, t; }"
        : "=r"(a) : "l"(p));
    return a;
}
__device__ __forceinline__ void cpasync16(uint32_t dst, const void* src, int sz) {
    asm volatile("cp.async.cg.shared.global [%0], [%1], 16, %2;"
                 :: "r"(dst), "l"(src), "r"(sz) : "memory");
}
#define CP_COMMIT() asm volatile("cp.async.commit_group;" ::: "memory")
#define CP_WAIT1()  asm volatile("cp.async.wait_group 1;" ::: "memory")
#define LDSM4(r0, r1, r2, r3, addr) \
    asm volatile("ldmatrix.sync.aligned.m8n8.x4.shared.b16 {%0,%1,%2,%3}, [%4];" \
        : "=r"(r0), "=r"(r1), "=r"(r2), "=r"(r3) : "r"(addr))
__device__ __forceinline__ void mma_f16(float* c, const uint32_t* a, const uint32_t* b) {
    asm volatile(
        "mma.sync.aligned.m16n8k16.row.col.f32.f16.f16.f32 "
        "{%0,%1,%2,%3}, {%4,%5,%6,%7}, {%8,%9}, {%0,%1,%2,%3};"
        : "+f"(c[0]), "+f"(c[1]), "+f"(c[2]), "+f"(c[3])
        : "r"(a[0]), "r"(a[1]), "r"(a[2]), "r"(a[3]), "r"(b[0]), "r"(b[1]));
}
__device__ __forceinline__ void mma_tf32(float* c, const uint32_t* a, const uint32_t* b) {
    asm volatile(
        "mma.sync.aligned.m16n8k8.row.col.f32.tf32.tf32.f32 "
        "{%0,%1,%2,%3}, {%4,%5,%6,%7}, {%8,%9}, {%0,%1,%2,%3};"
        : "+f"(c[0]), "+f"(c[1]), "+f"(c[2]), "+f"(c[3])
        : "r"(a[0]), "r"(a[1]), "r"(a[2]), "r"(a[3]), "r"(b[0]), "r"(b[1]));
}
__device__ __forceinline__ float warpReduceSum(float v) {
    #pragma unroll
    for (int o = 16; o > 0; o >>= 1) v += __shfl_xor_sync(0xffffffffu, v, o);
    return v;
}
__device__ __forceinline__ float warpReduceMax(float v) {
    #pragma unroll
    for (int o = 16; o > 0; o >>= 1) v = fmaxf(v, __shfl_xor_sync(0xffffffffu, v, o));
    return v;
}

// ---------------- generic GEMM descriptor ----------------
struct GDesc {
    const void* A; const void* B; const float* bias; float* C;
    __half* sideout;
    int lda, ldb, ldc, N, K, KC;
    long zstride;
    int ntiles, ctasPerZ, nCtas;
};
struct ConvSegs {
    const float* src[5];
    __half* dst[5];
    int srcld[5], K[5], Kp[5];
    long start[6];
};
#define TMMA_SMEM 98304

// ================= tf32 GEMM body (fp32 inputs): C = A(M,K) @ B(N,K)^T ============
__device__ __forceinline__ void tmma_issue_f(
    uint32_t smbase, int p, int kk, int kend,
    const float* A, int lda, const float* B, int ldb,
    int m0, int n0, int N, int lr, int c16)
{
    const int kc = kk + (c16 << 2);
    const bool kok = (kc + 4 <= kend);
    const int szk = kok ? 16 : 0;
    #pragma unroll
    for (int i = 0; i < 4; i++) {
        int row = lr + (i << 5);
        const float* src = kok ? (A + (size_t)(m0 + row) * lda + kc) : A;
        uint32_t dst = smbase + p * 32768 + row * 128 + ((c16 ^ (row & 7)) << 4);
        cpasync16(dst, src, szk);
    }
    #pragma unroll
    for (int i = 0; i < 4; i++) {
        int row = lr + (i << 5);
        int n = n0 + row;
        bool ok = kok && (n < N);
        int sz = ok ? 16 : 0;
        const float* src = ok ? (B + (size_t)n * ldb + kc) : B;
        uint32_t dst = smbase + p * 32768 + 16384 + row * 128 + ((c16 ^ (row & 7)) << 4);
        cpasync16(dst, src, sz);
    }
    CP_COMMIT();
}

__device__ __forceinline__ void gemm_f32(const GDesc& d, int bx, uint32_t* sm)
{
    const int tid = threadIdx.x;
    const int lane = tid & 31, wid = tid >> 5;
    const int wm = wid & 1, wn = wid >> 1;
    const int gid = lane >> 2, tg = lane & 3;

    const int z = bx / d.ctasPerZ;
    const int r = bx % d.ctasPerZ;
    const int m0 = (r / d.ntiles) << 7;
    const int n0 = (r % d.ntiles) << 7;
    const int N = d.N, lda = d.lda, ldb = d.ldb, ldc = d.ldc;
    const float* A = (const float*)d.A;
    const float* B = (const float*)d.B;
    const int kstart = z * d.KC;
    int kend = kstart + d.KC; if (kend > d.K) kend = d.K;
    const int nb = (kend - kstart + 31) >> 5;

    const uint32_t smbase = smem_u32(sm);
    const int lr = tid >> 3, c16 = tid & 7;

    const int ahi = (lane >> 4) & 1;
    const int bhi = (lane >> 3) & 1;
    uint32_t aoff[4]; int asw[4];
    #pragma unroll
    for (int mt = 0; mt < 4; mt++) {
        int rr = wm * 64 + mt * 16 + (lane & 7) + (lane & 8);
        aoff[mt] = rr * 128;
        asw[mt] = rr & 7;
    }
    uint32_t boff[2]; int bsw[2];
    #pragma unroll
    for (int nn = 0; nn < 2; nn++) {
        int rr = wn * 32 + nn * 16 + (lane & 7) + ((lane & 16) >> 1);
        boff[nn] = 16384 + rr * 128;
        bsw[nn] = rr & 7;
    }

    float c[4][4][4];
    #pragma unroll
    for (int i = 0; i < 4; i++)
        #pragma unroll
        for (int j = 0; j < 4; j++)
            #pragma unroll
            for (int q = 0; q < 4; q++) c[i][j][q] = 0.f;

    const int sr = tid >> 1;
    const int scb = (tid & 1) * 4;
    __half* so = d.sideout;

    tmma_issue_f(smbase, 0, kstart, kend, A, lda, B, ldb, m0, n0, N, lr, c16);
    if (nb > 1)
        tmma_issue_f(smbase, 1, kstart + 32, kend, A, lda, B, ldb, m0, n0, N, lr, c16);
    else
        CP_COMMIT();

    for (int kb = 0; kb < nb; kb++) {
        CP_WAIT1();
        __syncthreads();
        const uint32_t sp = smbase + (kb % 3) * 32768;
        #pragma unroll
        for (int ks = 0; ks < 4; ks++) {
            uint32_t af[4][4], bf[4][2];
            #pragma unroll
            for (int mt = 0; mt < 4; mt++) {
                uint32_t ad = sp + aoff[mt] + ((((ks << 1) + ahi) ^ asw[mt]) << 4);
                LDSM4(af[mt][0], af[mt][1], af[mt][2], af[mt][3], ad);
            }
            #pragma unroll
            for (int nn = 0; nn < 2; nn++) {
                uint32_t r0, r1, r2, r3;
                uint32_t bd = sp + boff[nn] + ((((ks << 1) + bhi) ^ bsw[nn]) << 4);
                LDSM4(r0, r1, r2, r3, bd);
                bf[nn * 2][0] = r0; bf[nn * 2][1] = r1;
                bf[nn * 2 + 1][0] = r2; bf[nn * 2 + 1][1] = r3;
            }
            #pragma unroll
            for (int mt = 0; mt < 4; mt++)
                #pragma unroll
                for (int nt = 0; nt < 4; nt++)
                    mma_tf32(c[mt][nt], af[mt], bf[nt]);
        }
        if (so) {
            const char* base = (const char*)sm + (size_t)(kb % 3) * 32768 + sr * 128;
            __half2 hb[8];
            #pragma unroll
            for (int j = 0; j < 4; j++) {
                float4 v = *(const float4*)(base + (((scb + j) ^ (sr & 7)) << 4));
                hb[2 * j]     = __floats2half2_rn(v.x, v.y);
                hb[2 * j + 1] = __floats2half2_rn(v.z, v.w);
            }
            __half* dstp = so + (size_t)(m0 + sr) * lda + (kstart + kb * 32 + scb * 4);
            const uint4* u = (const uint4*)hb;
            *(uint4*)dstp = u[0];
            *(uint4*)(dstp + 8) = u[1];
        }
        const int nk = kb + 2;
        if (nk < nb)
            tmma_issue_f(smbase, nk % 3, kstart + nk * 32, kend,
                         A, lda, B, ldb, m0, n0, N, lr, c16);
        else
            CP_COMMIT();
    }

    const float* bias = d.bias;
    float* Cz = d.C + (size_t)z * d.zstride;
    #pragma unroll
    for (int mt = 0; mt < 4; mt++) {
        int r0 = m0 + wm * 64 + mt * 16 + gid;
        #pragma unroll
        for (int nt = 0; nt < 4; nt++) {
            int cc = n0 + wn * 32 + nt * 8 + 2 * tg;
            float* p0 = Cz + (size_t)r0 * ldc + cc;
            float* p1 = p0 + 8 * ldc;
            if (cc < N) {
                float bb = bias ? bias[cc] : 0.f;
                p0[0] = c[mt][nt][0] + bb;
                p1[0] = c[mt][nt][2] + bb;
            }
            if (cc + 1 < N) {
                float bb = bias ? bias[cc + 1] : 0.f;
                p0[1] = c[mt][nt][1] + bb;
                p1[1] = c[mt][nt][3] + bb;
            }
        }
    }
}

// ================= fp16 GEMM body: BK=64 halfs ================
__device__ __forceinline__ void tmma_issue_h(
    uint32_t smbase, int p, int kk, int kend,
    const __half* A, int lda, const __half* B, int ldb,
    int m0, int n0, int N, int lr, int c16)
{
    const int kc = kk + (c16 << 3);
    const bool kok = (kc + 8 <= kend);
    const int szk = kok ? 16 : 0;
    #pragma unroll
    for (int i = 0; i < 4; i++) {
        int row = lr + (i << 5);
        const __half* src = kok ? (A + (size_t)(m0 + row) * lda + kc) : A;
        uint32_t dst = smbase + p * 32768 + row * 128 + ((c16 ^ (row & 7)) << 4);
        cpasync16(dst, src, szk);
    }
    #pragma unroll
    for (int i = 0; i < 4; i++) {
        int row = lr + (i << 5);
        int n = n0 + row;
        bool ok = kok && (n < N);
        int sz = ok ? 16 : 0;
        const __half* src = ok ? (B + (size_t)n * ldb + kc) : B;
        uint32_t dst = smbase + p * 32768 + 16384 + row * 128 + ((c16 ^ (row & 7)) << 4);
        cpasync16(dst, src, sz);
    }
    CP_COMMIT();
}

__device__ __forceinline__ void gemm_f16(const GDesc& d, int bx, uint32_t* sm)
{
    const int tid = threadIdx.x;
    const int lane = tid & 31, wid = tid >> 5;
    const int wm = wid & 1, wn = wid >> 1;
    const int gid = lane >> 2, tg = lane & 3;

    const int z = bx / d.ctasPerZ;
    const int r = bx % d.ctasPerZ;
    const int m0 = (r / d.ntiles) << 7;
    const int n0 = (r % d.ntiles) << 7;
    const int N = d.N, lda = d.lda, ldb = d.ldb, ldc = d.ldc;
    const __half* A = (const __half*)d.A;
    const __half* B = (const __half*)d.B;
    const int kstart = z * d.KC;
    int kend = kstart + d.KC; if (kend > d.K) kend = d.K;
    const int nb = (kend - kstart + 63) >> 6;

    const uint32_t smbase = smem_u32(sm);
    const int lr = tid >> 3, c16 = tid & 7;

    const int ahi = lane >> 4;
    const int bhi = (lane >> 3) & 1;
    uint32_t aoff[4]; int asw[4];
    #pragma unroll
    for (int mt = 0; mt < 4; mt++) {
        int rr = wm * 64 + mt * 16 + (lane & 15);
        aoff[mt] = rr * 128;
        asw[mt] = rr & 7;
    }
    uint32_t boff[2]; int bsw[2];
    #pragma unroll
    for (int nn = 0; nn < 2; nn++) {
        int rr = wn * 32 + nn * 16 + (lane & 7) + ((lane & 16) >> 1);
        boff[nn] = 16384 + rr * 128;
        bsw[nn] = rr & 7;
    }

    float c[4][4][4];
    #pragma unroll
    for (int i = 0; i < 4; i++)
        #pragma unroll
        for (int j = 0; j < 4; j++)
            #pragma unroll
            for (int q = 0; q < 4; q++) c[i][j][q] = 0.f;

    tmma_issue_h(smbase, 0, kstart, kend, A, lda, B, ldb, m0, n0, N, lr, c16);
    if (nb > 1)
        tmma_issue_h(smbase, 1, kstart + 64, kend, A, lda, B, ldb, m0, n0, N, lr, c16);
    else
        CP_COMMIT();

    for (int kb = 0; kb < nb; kb++) {
        CP_WAIT1();
        __syncthreads();
        const uint32_t sp = smbase + (kb % 3) * 32768;
        #pragma unroll
        for (int ks = 0; ks < 4; ks++) {
            uint32_t af[4][4], bf[4][2];
            #pragma unroll
            for (int mt = 0; mt < 4; mt++) {
                uint32_t ad = sp + aoff[mt] + ((((ks << 1) + ahi) ^ asw[mt]) << 4);
                LDSM4(af[mt][0], af[mt][1], af[mt][2], af[mt][3], ad);
            }
            #pragma unroll
            for (int nn = 0; nn < 2; nn++) {
                uint32_t r0, r1, r2, r3;
                uint32_t bd = sp + boff[nn] + ((((ks << 1) + bhi) ^ bsw[nn]) << 4);
                LDSM4(r0, r1, r2, r3, bd);
                bf[nn * 2][0] = r0; bf[nn * 2][1] = r1;
                bf[nn * 2 + 1][0] = r2; bf[nn * 2 + 1][1] = r3;
            }
            #pragma unroll
            for (int mt = 0; mt < 4; mt++)
                #pragma unroll
                for (int nt = 0; nt < 4; nt++)
                    mma_f16(c[mt][nt], af[mt], bf[nt]);
        }
        const int nk = kb + 2;
        if (nk < nb)
            tmma_issue_h(smbase, nk % 3, kstart + nk * 64, kend,
                         A, lda, B, ldb, m0, n0, N, lr, c16);
        else
            CP_COMMIT();
    }

    const float* bias = d.bias;
    float* Cz = d.C + (size_t)z * d.zstride;
    #pragma unroll
    for (int mt = 0; mt < 4; mt++) {
        int r0 = m0 + wm * 64 + mt * 16 + gid;
        #pragma unroll
        for (int nt = 0; nt < 4; nt++) {
            int cc = n0 + wn * 32 + nt * 8 + 2 * tg;
            float* p0 = Cz + (size_t)r0 * ldc + cc;
            float* p1 = p0 + 8 * ldc;
            if (cc < N) {
                float bb = bias ? bias[cc] : 0.f;
                p0[0] = c[mt][nt][0] + bb;
                p1[0] = c[mt][nt][2] + bb;
            }
            if (cc + 1 < N) {
                float bb = bias ? bias[cc + 1] : 0.f;
                p0[1] = c[mt][nt][1] + bb;
                p1[1] = c[mt][nt][3] + bb;
            }
        }
    }
}

// ====== mega launch: 3 tf32 GEMMs + 1 fp16 GEMM (named params, static dispatch) =====
__global__ void __launch_bounds__(256, 2) tmma4(GDesc d0, GDesc d1, GDesc d2, GDesc e0)
{
    extern __shared__ __align__(1024) uint32_t sm[];
    int bx = blockIdx.x;
    const int n0 = d0.nCtas, n01 = n0 + d1.nCtas, n012 = n01 + d2.nCtas;
    if (bx < n012) {
        const GDesc& d = (bx < n0) ? d0 : ((bx < n01) ? d1 : d2);
        if (bx >= n0) bx -= n0;
        if (&d == &d2) bx -= d1.nCtas;
        gemm_f32(d, bx, sm);
    } else {
        gemm_f16(e0, bx - n012, sm);
    }
}

// ================= prep: weight convert (5 segs) + embedding staging =================
__global__ void prep_kernel(ConvSegs cs,
                            const int* __restrict__ input,
                            const int* __restrict__ input_d,
                            const float* __restrict__ hidden,
                            const float* __restrict__ ans,
                            const float* __restrict__ emb_w,
                            const float* __restrict__ emb_d_w,
                            float* __restrict__ aheadF,
                            __half* __restrict__ minpH)
{
    if (blockIdx.x < BB) {
        int b = blockIdx.x, t = threadIdx.x;  // 256
        int tok = input[b];
        const float* src;
        if (tok > 2003) {
            int di = tok - 2004;
            if (di > LCC - 1) di = LCC - 1;
            if (di < 0) di = 0;
            int dt = input_d[b * LCC + di];
            src = emb_d_w + (size_t)dt * EE;
        } else {
            int tv = tok < 0 ? 0 : tok;
            src = emb_w + (size_t)tv * EE;
        }
        float* ah = aheadF + (size_t)b * AHEAD_K;
        __half* mp = minpH + (size_t)b * MINP_LD;
        for (int j = t; j < EE; j += 256) {
            float e = src[j];
            ah[512 + j] = e;
            mp[1536 + j] = __float2half_rn(e);
        }
        for (int h = t; h < HH; h += 256) {
            float hv = hidden[(size_t)b * HH + h];
            float av = ans[(size_t)b * HH + h];
            ah[h] = hv;
            ah[812 + h] = av;
            mp[1024 + h] = __float2half_rn(av);
        }
        if (t < 4) mp[1836 + t] = __float2half_rn(0.f);
    } else {
        long total = cs.start[5] >> 3;
        long stride = 2048L * 256;
        for (long gidx = (long)(blockIdx.x - BB) * 256 + threadIdx.x;
             gidx < total; gidx += stride) {
            long e = gidx << 3;
            int s = 0;
            #pragma unroll
            for (int j = 0; j < 4; j++) if (e >= cs.start[j + 1]) s = j + 1;
            long loc = e - cs.start[s];
            int Kp = cs.Kp[s];
            long row = loc / Kp;
            int col = (int)(loc - row * Kp);
            const float* src = cs.src[s] + row * (long)cs.srcld[s] + col;
            int K = cs.K[s];
            __half2 h[4];
            if (col + 8 <= K) {
                float4 v0 = *(const float4*)src;
                float4 v1 = *(const float4*)(src + 4);
                h[0] = __floats2half2_rn(v0.x, v0.y);
                h[1] = __floats2half2_rn(v0.z, v0.w);
                h[2] = __floats2half2_rn(v1.x, v1.y);
                h[3] = __floats2half2_rn(v1.z, v1.w);
            } else {
                float tt[8];
                #pragma unroll
                for (int j = 0; j < 8; j++) tt[j] = (col + j < K) ? src[j] : 0.f;
                h[0] = __floats2half2_rn(tt[0], tt[1]);
                h[1] = __floats2half2_rn(tt[2], tt[3]);
                h[2] = __floats2half2_rn(tt[4], tt[5]);
                h[3] = __floats2half2_rn(tt[6], tt[7]);
            }
            *(uint4*)(cs.dst[s] + loc) = *(uint4*)h;
        }
    }
}

// ---------------- K3: partials reduce + tanh + softmax + fused c_t (fp16 annot) ----
__global__ void attn_finalize_ct(const float* __restrict__ partial,
                                 const float* __restrict__ attn_b,
                                 const __half* __restrict__ annotH,
                                 float* __restrict__ attnw,
                                 __half* __restrict__ minpH)
{
    __shared__ float pacc[512];
    __shared__ float sred[16];
    __shared__ float wsm[128];
    __shared__ float cacc[4096];
    int b = blockIdx.x, t = threadIdx.x;  // 512

    {
        int g = t >> 7, l = t & 127;
        const float* pb = partial + (size_t)b * (NSPLIT * LCC);
        float acc = 0.f;
        if (l < LCC) {
            int s0 = g * 17;
            #pragma unroll
            for (int s = 0; s < 17; s++) acc += pb[(s0 + s) * LCC + l];
        }
        pacc[t] = acc;
    }
    __syncthreads();
    float v = -1e30f;
    if (t < LCC)
        v = tanhf(attn_b[t] + pacc[t] + pacc[128 + t] + pacc[256 + t] + pacc[384 + t]);
    float m = warpReduceMax(v);
    if ((t & 31) == 0) sred[t >> 5] = m;
    __syncthreads();
    float mm = sred[0];
    #pragma unroll
    for (int w = 1; w < 16; w++) mm = fmaxf(mm, sred[w]);
    float e = (t < LCC) ? __expf(v - mm) : 0.f;
    float ss = warpReduceSum(e);
    __syncthreads();
    if ((t & 31) == 0) sred[t >> 5] = ss;
    __syncthreads();
    float tot = 0.f;
    #pragma unroll
    for (int w = 0; w < 16; w++) tot += sred[w];
    if (t < LCC) {
        float wv = e / tot;
        attnw[(size_t)b * LCC + t] = wv;
        wsm[t] = wv;
    }
    __syncthreads();

    {
        int chunk = t & 63;
        int g2 = t >> 6;
        const __half* Ab = annotH + (size_t)b * ANNOT_K + chunk * 8;
        float acc8[8];
        #pragma unroll
        for (int j = 0; j < 8; j++) acc8[j] = 0.f;
        int l = g2;
        for (; l + 24 < LCC; l += 32) {
            uint4 r0 = *(const uint4*)(Ab + (size_t)l * 512);
            uint4 r1 = *(const uint4*)(Ab + (size_t)(l + 8) * 512);
            uint4 r2 = *(const uint4*)(Ab + (size_t)(l + 16) * 512);
            uint4 r3 = *(const uint4*)(Ab + (size_t)(l + 24) * 512);
            float w0 = wsm[l], w1 = wsm[l + 8], w2 = wsm[l + 16], w3 = wsm[l + 24];
            const __half2* h0 = (const __half2*)&r0;
            const __half2* h1 = (const __half2*)&r1;
            const __half2* h2 = (const __half2*)&r2;
            const __half2* h3 = (const __half2*)&r3;
            #pragma unroll
            for (int j = 0; j < 4; j++) {
                float2 f0 = __half22float2(h0[j]);
                float2 f1 = __half22float2(h1[j]);
                float2 f2 = __half22float2(h2[j]);
                float2 f3 = __half22float2(h3[j]);
                acc8[2 * j]     += w0 * f0.x + w1 * f1.x + w2 * f2.x + w3 * f3.x;
                acc8[2 * j + 1] += w0 * f0.y + w1 * f1.y + w2 * f2.y + w3 * f3.y;
            }
        }
        for (; l < LCC; l += 8) {
            uint4 r0 = *(const uint4*)(Ab + (size_t)l * 512);
            float w0 = wsm[l];
            const __half2* h0 = (const __half2*)&r0;
            #pragma unroll
            for (int j = 0; j < 4; j++) {
                float2 f0 = __half22float2(h0[j]);
                acc8[2 * j]     = fmaf(w0, f0.x, acc8[2 * j]);
                acc8[2 * j + 1] = fmaf(w0, f0.y, acc8[2 * j + 1]);
            }
        }
        #pragma unroll
        for (int j = 0; j < 8; j++) cacc[g2 * 512 + chunk * 8 + j] = acc8[j];
    }
    __syncthreads();
    {
        float s = 0.f;
        #pragma unroll
        for (int g = 0; g < 8; g++) s += cacc[g * 512 + t];
        minpH[(size_t)b * MINP_LD + 512 + t] = __float2half_rn(s);
    }
}

// ================= persistent tail: gi -> gru -> mlp/z1 -> combine -> out/z2 -> final
__global__ void __launch_bounds__(256, 2) tail_kernel(
    GDesc dGIC, GDesc dML, GDesc dZ1, GDesc dOU, GDesc dZ2,
    const float* __restrict__ giS, const float* __restrict__ giC,
    const float* __restrict__ gh, const float* __restrict__ b_ih,
    const float* __restrict__ h0, __half* __restrict__ minpH,
    float* __restrict__ out0, float* __restrict__ out1,
    const float* __restrict__ etP, const float* __restrict__ mlp_b,
    __half* __restrict__ etH,
    const float* __restrict__ z1P, const float* __restrict__ zt_b1,
    __half* __restrict__ z1H,
    const float* __restrict__ ologP, const float* __restrict__ out_b,
    const float* __restrict__ z2P, const float* __restrict__ zt_b2,
    const float* __restrict__ zt_W3, const float* __restrict__ zt_b3,
    const float* __restrict__ attnw, float* __restrict__ pout)
{
    extern __shared__ __align__(1024) uint32_t sm[];
    const int tid = threadIdx.x;
    const int gtid = blockIdx.x * 256 + tid;
    const int gstride = gridDim.x * 256;

    // ---- P0: gi dynamic (c_t) GEMM ----
    for (int v = blockIdx.x; v < dGIC.nCtas; v += gridDim.x)
        gemm_f16(dGIC, v, sm);
    gridbar();

    // ---- P1: GRU elementwise ----
    for (int i = gtid; i < BB * HH; i += gstride) {
        int b = i >> 9, h = i & 511;
        size_t o = (size_t)b * 1536;
        const float* gs = giS + o;
        const float* c0 = giC + o;
        const float* c1 = giC + 786432 + o;
        const float* q = gh + o;
        float ir = gs[h] + c0[h] + c1[h] + b_ih[h];
        float iz = gs[512 + h] + c0[512 + h] + c1[512 + h] + b_ih[512 + h];
        float in_ = gs[1024 + h] + c0[1024 + h] + c1[1024 + h] + b_ih[1024 + h];
        float r = 1.f / (1.f + __expf(-(ir + q[h])));
        float z = 1.f / (1.f + __expf(-(iz + q[512 + h])));
        float n = tanhf(in_ + r * q[1024 + h]);
        float hnew = (1.f - z) * n + z * h0[i];
        minpH[(size_t)b * MINP_LD + h] = __float2half_rn(hnew);
        out0[i] = hnew;
        out1[i] = hnew;
    }
    gridbar();

    // ---- P2: mlp (z=8) + z1 (z=4) GEMMs ----
    for (int v = blockIdx.x; v < dML.nCtas + dZ1.nCtas; v += gridDim.x) {
        if (v < dML.nCtas) gemm_f16(dML, v, sm);
        else               gemm_f16(dZ1, v - dML.nCtas, sm);
    }
    gridbar();

    // ---- P3: combine (et: 8 parts | z1: 4 parts + tanh) ----
    for (int i = gtid; i < 262144; i += gstride) {
        float v = mlp_b[i & 511];
        #pragma unroll
        for (int j = 0; j < 8; j++) v += etP[i + (size_t)j * 262144];
        etH[i] = __float2half_rn(v);
    }
    for (int i = gtid; i < 524288; i += gstride) {
        float v = zt_b1[i & 1023];
        #pragma unroll
        for (int j = 0; j < 4; j++) v += z1P[i + (size_t)j * 524288];
        z1H[i] = __float2half_rn(tanhf(v));
    }
    gridbar();

    // ---- P4: out head (z=2) + z2 (z=4) GEMMs ----
    for (int v = blockIdx.x; v < dOU.nCtas + dZ2.nCtas; v += gridDim.x) {
        if (v < dOU.nCtas) gemm_f16(dOU, v, sm);
        else               gemm_f16(dZ2, v - dOU.nCtas, sm);
    }
    gridbar();

    // ---- P5: final (dynamic smem; virtual blocks over b) ----
    {
        float* buf  = (float*)sm;           // OO floats
        float* sred = buf + OO;             // 16
        float* sbc  = sred + 16;            // 1
        for (int b = blockIdx.x; b < BB; b += gridDim.x) {
            size_t o = (size_t)b * HH;
            float zt;
            {
                float zv = 0.f, s = 0.f;
                #pragma unroll
                for (int rep = 0; rep < 2; rep++) {
                    int h = tid + rep * 256;
                    float zz = z2P[o + h] + z2P[262144 + o + h] +
                               z2P[524288 + o + h] + z2P[786432 + o + h] + zt_b2[h];
                    zz = tanhf(zz);
                    s += zz * zt_W3[h];
                    (void)zv;
                }
                s = warpReduceSum(s);
                if ((tid & 31) == 0) sred[tid >> 5] = s;
                __syncthreads();
                if (tid == 0) {
                    float tot = 0.f;
                    for (int w = 0; w < 8; w++) tot += sred[w];
                    sbc[0] = 1.f / (1.f + __expf(-(tot + zt_b3[0])));
                }
                __syncthreads();
                zt = sbc[0];
            }

            const float* ob0 = ologP + (size_t)b * OO;
            const float* ob1 = ob0 + (size_t)BB * OO;
            float mx = -1e30f;
            for (int j = tid; j < OO; j += 256) {
                float v = ob0[j] + ob1[j] + out_b[j];
                buf[j] = v;
                mx = fmaxf(mx, v);
            }
            mx = warpReduceMax(mx);
            __syncthreads();
            if ((tid & 31) == 0) sred[tid >> 5] = mx;
            __syncthreads();
            if (tid == 0) {
                float m2 = sred[0];
                for (int w = 1; w < 8; w++) m2 = fmaxf(m2, sred[w]);
                sbc[0] = m2;
            }
            __syncthreads();
            mx = sbc[0];

            float se = 0.f;
            for (int j = tid; j < OO; j += 256) {
                float e = __expf(buf[j] - mx);
                buf[j] = e;
                se += e;
            }
            se = warpReduceSum(se);
            __syncthreads();
            if ((tid & 31) == 0) sred[tid >> 5] = se;
            __syncthreads();
            if (tid == 0) {
                float tot = 0.f;
                for (int w = 0; w < 8; w++) tot += sred[w];
                sbc[0] = tot;
            }
            __syncthreads();
            float cc = zt / sbc[0];

            float* pb = pout + (size_t)b * (OO + LCC);
            for (int j = tid; j < OO; j += 256)
                pb[j] = __logf(buf[j] * cc + 1e-20f);
            float omz = 1.f - zt;
            for (int l = tid; l < LCC; l += 256)
                pb[OO + l] = __logf(attnw[(size_t)b * LCC + l] * omz + 1e-20f);
            __syncthreads();
        }
    }
}

// ---------------- launch ----------------
static GDesc mkdesc(const void* A, int lda, const void* B, int ldb,
                    const float* bias, float* C, int ldc,
                    int M, int N, int K, int KC, long zstride, int zcount,
                    __half* sideout = nullptr)
{
    GDesc d;
    d.A = A; d.B = B; d.bias = bias; d.C = C; d.sideout = sideout;
    d.lda = lda; d.ldb = ldb; d.ldc = ldc;
    d.N = N; d.K = K; d.KC = KC; d.zstride = zstride;
    d.ntiles = (N + 127) / 128;
    d.ctasPerZ = (M / 128) * d.ntiles;
    d.nCtas = d.ctasPerZ * zcount;
    return d;
}

extern "C" void kernel_launch(void* const* d_in, const int* in_sizes, int n_in,
                              void* d_out, int out_size)
{
    const int*   input   = (const int*)d_in[0];
    const int*   input_d = (const int*)d_in[1];
    const float* hidden  = (const float*)d_in[2];
    const float* annot   = (const float*)d_in[3];
    const float* ans     = (const float*)d_in[4];
    const float* emb_w   = (const float*)d_in[5];
    const float* emb_d_w = (const float*)d_in[6];
    const float* attn_W  = (const float*)d_in[7];
    const float* attn_b  = (const float*)d_in[8];
    const float* W_ih    = (const float*)d_in[9];
    const float* W_hh    = (const float*)d_in[10];
    const float* b_ih    = (const float*)d_in[11];
    const float* b_hh    = (const float*)d_in[12];
    const float* mlp_W   = (const float*)d_in[13];
    const float* mlp_b   = (const float*)d_in[14];
    const float* out_W   = (const float*)d_in[15];
    const float* out_b   = (const float*)d_in[16];
    const float* zt_W1   = (const float*)d_in[17];
    const float* zt_b1   = (const float*)d_in[18];
    const float* zt_W2   = (const float*)d_in[19];
    const float* zt_b2   = (const float*)d_in[20];
    const float* zt_W3   = (const float*)d_in[21];
    const float* zt_b3   = (const float*)d_in[22];
    float* out = (float*)d_out;

    float* f32 = nullptr;  __half* f16 = nullptr;
    cudaGetSymbolAddress((void**)&f32, g_f32);
    cudaGetSymbolAddress((void**)&f16, g_f16);

    float* part   = f32 + OFF_PART;
    float* attnw  = f32 + OFF_ATTNW;
    float* giS    = f32 + OFF_GIS;
    float* giC    = f32 + OFF_GICP;
    float* gh     = f32 + OFF_GH;
    float* etP    = f32 + OFF_ETP;
    float* ologP  = f32 + OFF_OLOGP;
    float* z1P    = f32 + OFF_Z1P;
    float* z2P    = f32 + OFF_Z2P;
    float* aheadF = f32 + OFF_AHEAD;

    __half* annotH = f16 + HOFF_ANNOT;
    __half* WihH   = f16 + HOFF_WIH;
    __half* mlpWH  = f16 + HOFF_MLPW;
    __half* outWH  = f16 + HOFF_OUTW;
    __half* z1WH   = f16 + HOFF_Z1W;
    __half* z2WH   = f16 + HOFF_Z2W;
    __half* minpH  = f16 + HOFF_MINP;
    __half* etH    = f16 + HOFF_ET;
    __half* z1H    = f16 + HOFF_Z1;

    cudaFuncSetAttribute(tmma4, cudaFuncAttributeMaxDynamicSharedMemorySize, TMMA_SMEM);
    cudaFuncSetAttribute(tail_kernel, cudaFuncAttributeMaxDynamicSharedMemorySize, TMMA_SMEM);

    // persistent grid: all CTAs resident (deadlock-free by construction)
    int dev = 0, sms = 0, perSM = 0;
    cudaGetDevice(&dev);
    cudaDeviceGetAttribute(&sms, cudaDevAttrMultiProcessorCount, dev);
    cudaOccupancyMaxActiveBlocksPerMultiprocessor(&perSM, tail_kernel, 256, TMMA_SMEM);
    if (perSM < 1) perSM = 1;
    if (perSM > 2) perSM = 2;
    int tailGrid = sms * perSM;

    // 0. prep: weight convert + embedding staging
    ConvSegs cs;
    const float* srcs[5] = {W_ih, mlp_W, out_W, zt_W1, zt_W2};
    __half* dsts[5] = {WihH, mlpWH, outWH, z1WH, z2WH};
    int slds[5] = {1324, 1836, 512, 1836, 1024};
    int Ks[5]   = {1324, 1836, 512, 1836, 1024};
    int Kps[5]  = {1328, 1840, 512, 1840, 1024};
    long rows[5] = {1536, 512, 2004, 1024, 512};
    long acc = 0;
    for (int i = 0; i < 5; i++) {
        cs.src[i] = srcs[i]; cs.dst[i] = dsts[i];
        cs.srcld[i] = slds[i]; cs.K[i] = Ks[i]; cs.Kp[i] = Kps[i];
        cs.start[i] = acc;
        acc += rows[i] * Kps[i];
    }
    cs.start[5] = acc;
    prep_kernel<<<BB + 2048, 256>>>(cs, input, input_d, hidden, ans,
                                    emb_w, emb_d_w, aheadF, minpH);

    // 2. mega launch: attn-annot (tf32, z=64, sideout) + attn-head (tf32, z=4)
    //    + gh (tf32) + gi-static over [ans|emb] (fp16, K=816)
    GDesc dAA = mkdesc(annot, ANNOT_K, attn_W + AHEAD_K, 52524, nullptr,
                       part, NSPLIT * LCC, BB, LCC, ANNOT_K, 800, LCC, 64, annotH);
    GDesc dAH = mkdesc(aheadF, AHEAD_K, attn_W, 52524, nullptr,
                       part + 64 * LCC, NSPLIT * LCC, BB, LCC, AHEAD_K, 332, LCC, 4);
    GDesc dGH = mkdesc(hidden, HH, W_hh, HH, b_hh,
                       gh, 1536, BB, 1536, HH, HH, 0, 1);
    GDesc eGIS = mkdesc(minpH + 1024, MINP_LD, WihH + 512, WIH_LD, nullptr,
                        giS, 1536, BB, 1536, 816, 816, 0, 1);
    tmma4<<<dAA.nCtas + dAH.nCtas + dGH.nCtas + eGIS.nCtas, 256, TMMA_SMEM>>>(
        dAA, dAH, dGH, eGIS);

    // 3. finalize + fused c_t
    attn_finalize_ct<<<BB, 512>>>(part, attn_b, annotH, attnw, minpH);

    // 4. persistent tail: gi-dyn -> gru -> mlp/z1 -> combine -> out/z2 -> final
    GDesc dGIC = mkdesc(minpH + 512, MINP_LD, WihH, WIH_LD, nullptr,
                        giC, 1536, BB, 1536, 512, 256, 786432, 2);
    GDesc dML = mkdesc(minpH, MINP_LD, mlpWH, MINP_LD, nullptr,
                       etP, HH, BB, HH, MINP_LD, 232, 262144, 8);
    GDesc dZ1 = mkdesc(minpH, MINP_LD, z1WH, MINP_LD, nullptr,
                       z1P, 1024, BB, 1024, MINP_LD, 464, 524288, 4);
    GDesc dOU = mkdesc(etH, HH, outWH, HH, nullptr,
                       ologP, OO, BB, OO, HH, 256, (long)BB * OO, 2);
    GDesc dZ2 = mkdesc(z1H, 1024, z2WH, 1024, nullptr,
                       z2P, HH, BB, HH, 1024, 256, 262144, 4);
    tail_kernel<<<tailGrid, 256, TMMA_SMEM>>>(
        dGIC, dML, dZ1, dOU, dZ2,
        giS, giC, gh, b_ih, hidden, minpH, out, out + BB * HH,
        etP, mlp_b, etH, z1P, zt_b1, z1H,
        ologP, out_b, z2P, zt_b2, zt_W3, zt_b3, attnw,
        out + 2 * BB * HH);
}

// round 17
// speedup vs baseline: 1.0941x; 1.0941x over previous
#include <cuda_runtime.h>
#include <cuda_fp16.h>
#include <cstdint>
#include <math.h>

// ---------------- problem constants ----------------
#define BB 512
#define HH 512
#define EE 300
#define LCC 100
#define OO 2004
#define ANNOT_K 51200
#define NSPLIT 68          // 64 annot + 4 head splits
#define AHEAD_K 1324
#define MINP_LD 1840       // fp16 minp row: [h_new|c_t|ans|emb|pad4]
#define WIH_LD  1328       // 1324 padded

// ---------------- fp32 scratch ----------------
#define OFF_PART   0UL                   // 512*6800
#define OFF_ATTNW  3481600UL             // 512*100
#define OFF_GIP    3532800UL             // 3*512*1536 (gi split-K partials)
#define OFF_GH     5892096UL             // 512*1536
#define OFF_ETP    6678528UL             // 8*512*512
#define OFF_OLOGP  8775680UL             // 2*512*2004
#define OFF_Z1P    10827776UL            // 4*512*1024
#define OFF_Z2P    12924928UL            // 4*512*512
#define OFF_AHEAD  13973504UL            // 512*1324
#define F32_TOTAL  14651392UL

// ---------------- fp16 scratch ----------------
#define HOFF_ANNOT 0UL                   // 512*51200 (GEMM side-output)
#define HOFF_WIH   26214400UL            // 1536*1328
#define HOFF_MLPW  28254208UL            // 512*1840
#define HOFF_OUTW  29196288UL            // 2004*512
#define HOFF_Z1W   30222336UL            // 1024*1840
#define HOFF_Z2W   32106496UL            // 512*1024
#define HOFF_MINP  32630784UL            // 512*1840
#define HOFF_ET    33572864UL            // 512*512
#define HOFF_Z1    33835008UL            // 512*1024
#define F16_TOTAL  34359296UL

__device__ float g_f32[F32_TOTAL];
__device__ __align__(16) __half g_f16[F16_TOTAL];

// ---------------- low-level helpers ----------------
__device__ __forceinline__ uint32_t smem_u32(const void* p) {
    uint32_t a;
    asm("{ .reg .u64 t; cvta.to.shared.u64 t, %1; cvt.u32.u64 %0, t; }"
        : "=r"(a) : "l"(p));
    return a;
}
__device__ __forceinline__ void cpasync16(uint32_t dst, const void* src, int sz) {
    asm volatile("cp.async.cg.shared.global [%0], [%1], 16, %2;"
                 :: "r"(dst), "l"(src), "r"(sz) : "memory");
}
#define CP_COMMIT() asm volatile("cp.async.commit_group;" ::: "memory")
#define CP_WAIT1()  asm volatile("cp.async.wait_group 1;" ::: "memory")
#define LDSM4(r0, r1, r2, r3, addr) \
    asm volatile("ldmatrix.sync.aligned.m8n8.x4.shared.b16 {%0,%1,%2,%3}, [%4];" \
        : "=r"(r0), "=r"(r1), "=r"(r2), "=r"(r3) : "r"(addr))
__device__ __forceinline__ void mma_f16(float* c, const uint32_t* a, const uint32_t* b) {
    asm volatile(
        "mma.sync.aligned.m16n8k16.row.col.f32.f16.f16.f32 "
        "{%0,%1,%2,%3}, {%4,%5,%6,%7}, {%8,%9}, {%0,%1,%2,%3};"
        : "+f"(c[0]), "+f"(c[1]), "+f"(c[2]), "+f"(c[3])
        : "r"(a[0]), "r"(a[1]), "r"(a[2]), "r"(a[3]), "r"(b[0]), "r"(b[1]));
}
__device__ __forceinline__ void mma_tf32(float* c, const uint32_t* a, const uint32_t* b) {
    asm volatile(
        "mma.sync.aligned.m16n8k8.row.col.f32.tf32.tf32.f32 "
        "{%0,%1,%2,%3}, {%4,%5,%6,%7}, {%8,%9}, {%0,%1,%2,%3};"
        : "+f"(c[0]), "+f"(c[1]), "+f"(c[2]), "+f"(c[3])
        : "r"(a[0]), "r"(a[1]), "r"(a[2]), "r"(a[3]), "r"(b[0]), "r"(b[1]));
}
__device__ __forceinline__ float warpReduceSum(float v) {
    #pragma unroll
    for (int o = 16; o > 0; o >>= 1) v += __shfl_xor_sync(0xffffffffu, v, o);
    return v;
}
__device__ __forceinline__ float warpReduceMax(float v) {
    #pragma unroll
    for (int o = 16; o > 0; o >>= 1) v = fmaxf(v, __shfl_xor_sync(0xffffffffu, v, o));
    return v;
}

// ---------------- generic GEMM descriptor ----------------
struct GDesc {
    const void* A; const void* B; const float* bias; float* C;
    __half* sideout;      // optional fp16 copy of A (tf32 path only)
    int lda, ldb, ldc, N, K, KC;
    long zstride;
    int ntiles, ctasPerZ, nCtas;
};
#define TMMA_SMEM 98304

// ================= tf32 GEMM (fp32 inputs): C = A(M,K) @ B(N,K)^T =================
// BM=128, BN=128, BK=32 floats (128B rows, XOR-8 16B swizzle), 8 warps (2m x 4n),
// warp tile 64x32, 3-stage cp.async. Three fused descriptors. Optional fp16
// side-output of the A tile (each A element touched by exactly one CTA in split-K).
__device__ __forceinline__ void tmma_issue_f(
    uint32_t smbase, int p, int kk, int kend,
    const float* A, int lda, const float* B, int ldb,
    int m0, int n0, int N, int lr, int c16)
{
    const int kc = kk + (c16 << 2);
    const bool kok = (kc + 4 <= kend);
    const int szk = kok ? 16 : 0;
    #pragma unroll
    for (int i = 0; i < 4; i++) {
        int row = lr + (i << 5);
        const float* src = kok ? (A + (size_t)(m0 + row) * lda + kc) : A;
        uint32_t dst = smbase + p * 32768 + row * 128 + ((c16 ^ (row & 7)) << 4);
        cpasync16(dst, src, szk);
    }
    #pragma unroll
    for (int i = 0; i < 4; i++) {
        int row = lr + (i << 5);
        int n = n0 + row;
        bool ok = kok && (n < N);
        int sz = ok ? 16 : 0;
        const float* src = ok ? (B + (size_t)n * ldb + kc) : B;
        uint32_t dst = smbase + p * 32768 + 16384 + row * 128 + ((c16 ^ (row & 7)) << 4);
        cpasync16(dst, src, sz);
    }
    CP_COMMIT();
}

__global__ void __launch_bounds__(256, 2) tmma3f(GDesc d0, GDesc d1, GDesc d2)
{
    extern __shared__ __align__(1024) uint32_t sm[];
    const int tid = threadIdx.x;
    const int lane = tid & 31, wid = tid >> 5;
    const int wm = wid & 1, wn = wid >> 1;
    const int gid = lane >> 2, tg = lane & 3;

    int bx = blockIdx.x;
    const GDesc& d = (bx < d0.nCtas) ? d0 : ((bx < d0.nCtas + d1.nCtas) ? d1 : d2);
    if (bx >= d0.nCtas) bx -= d0.nCtas;
    if (&d == &d2) bx -= d1.nCtas;
    const int z = bx / d.ctasPerZ;
    const int r = bx % d.ctasPerZ;
    const int m0 = (r / d.ntiles) << 7;
    const int n0 = (r % d.ntiles) << 7;
    const int N = d.N, lda = d.lda, ldb = d.ldb, ldc = d.ldc;
    const float* A = (const float*)d.A;
    const float* B = (const float*)d.B;
    const int kstart = z * d.KC;
    int kend = kstart + d.KC; if (kend > d.K) kend = d.K;
    const int nb = (kend - kstart + 31) >> 5;

    const uint32_t smbase = smem_u32(sm);
    const int lr = tid >> 3, c16 = tid & 7;

    const int ahi = (lane >> 4) & 1;
    const int bhi = (lane >> 3) & 1;
    uint32_t aoff[4]; int asw[4];
    #pragma unroll
    for (int mt = 0; mt < 4; mt++) {
        int rr = wm * 64 + mt * 16 + (lane & 7) + (lane & 8);
        aoff[mt] = rr * 128;
        asw[mt] = rr & 7;
    }
    uint32_t boff[2]; int bsw[2];
    #pragma unroll
    for (int nn = 0; nn < 2; nn++) {
        int rr = wn * 32 + nn * 16 + (lane & 7) + ((lane & 16) >> 1);
        boff[nn] = 16384 + rr * 128;
        bsw[nn] = rr & 7;
    }

    float c[4][4][4];
    #pragma unroll
    for (int i = 0; i < 4; i++)
        #pragma unroll
        for (int j = 0; j < 4; j++)
            #pragma unroll
            for (int q = 0; q < 4; q++) c[i][j][q] = 0.f;

    const int sr = tid >> 1;
    const int scb = (tid & 1) * 4;
    __half* so = d.sideout;

    tmma_issue_f(smbase, 0, kstart, kend, A, lda, B, ldb, m0, n0, N, lr, c16);
    if (nb > 1)
        tmma_issue_f(smbase, 1, kstart + 32, kend, A, lda, B, ldb, m0, n0, N, lr, c16);
    else
        CP_COMMIT();

    for (int kb = 0; kb < nb; kb++) {
        CP_WAIT1();
        __syncthreads();
        const uint32_t sp = smbase + (kb % 3) * 32768;
        #pragma unroll
        for (int ks = 0; ks < 4; ks++) {
            uint32_t af[4][4], bf[4][2];
            #pragma unroll
            for (int mt = 0; mt < 4; mt++) {
                uint32_t ad = sp + aoff[mt] + ((((ks << 1) + ahi) ^ asw[mt]) << 4);
                LDSM4(af[mt][0], af[mt][1], af[mt][2], af[mt][3], ad);
            }
            #pragma unroll
            for (int nn = 0; nn < 2; nn++) {
                uint32_t r0, r1, r2, r3;
                uint32_t bd = sp + boff[nn] + ((((ks << 1) + bhi) ^ bsw[nn]) << 4);
                LDSM4(r0, r1, r2, r3, bd);
                bf[nn * 2][0] = r0; bf[nn * 2][1] = r1;
                bf[nn * 2 + 1][0] = r2; bf[nn * 2 + 1][1] = r3;
            }
            #pragma unroll
            for (int mt = 0; mt < 4; mt++)
                #pragma unroll
                for (int nt = 0; nt < 4; nt++)
                    mma_tf32(c[mt][nt], af[mt], bf[nt]);
        }
        if (so) {
            const char* base = (const char*)sm + (size_t)(kb % 3) * 32768 + sr * 128;
            __half2 hb[8];
            #pragma unroll
            for (int j = 0; j < 4; j++) {
                float4 v = *(const float4*)(base + (((scb + j) ^ (sr & 7)) << 4));
                hb[2 * j]     = __floats2half2_rn(v.x, v.y);
                hb[2 * j + 1] = __floats2half2_rn(v.z, v.w);
            }
            __half* dstp = so + (size_t)(m0 + sr) * lda + (kstart + kb * 32 + scb * 4);
            const uint4* u = (const uint4*)hb;
            *(uint4*)dstp = u[0];
            *(uint4*)(dstp + 8) = u[1];
        }
        const int nk = kb + 2;
        if (nk < nb)
            tmma_issue_f(smbase, nk % 3, kstart + nk * 32, kend,
                         A, lda, B, ldb, m0, n0, N, lr, c16);
        else
            CP_COMMIT();
    }

    const float* bias = d.bias;
    float* Cz = d.C + (size_t)z * d.zstride;
    #pragma unroll
    for (int mt = 0; mt < 4; mt++) {
        int r0 = m0 + wm * 64 + mt * 16 + gid;
        #pragma unroll
        for (int nt = 0; nt < 4; nt++) {
            int cc = n0 + wn * 32 + nt * 8 + 2 * tg;
            float* p0 = Cz + (size_t)r0 * ldc + cc;
            float* p1 = p0 + 8 * ldc;
            if (cc < N) {
                float bb = bias ? bias[cc] : 0.f;
                p0[0] = c[mt][nt][0] + bb;
                p1[0] = c[mt][nt][2] + bb;
            }
            if (cc + 1 < N) {
                float bb = bias ? bias[cc + 1] : 0.f;
                p0[1] = c[mt][nt][1] + bb;
                p1[1] = c[mt][nt][3] + bb;
            }
        }
    }
}

// ================= fp16 GEMM: C = A(M,K) @ B(N,K)^T, BK=64 halfs ================
__device__ __forceinline__ void tmma_issue_h(
    uint32_t smbase, int p, int kk, int kend,
    const __half* A, int lda, const __half* B, int ldb,
    int m0, int n0, int N, int lr, int c16)
{
    const int kc = kk + (c16 << 3);
    const bool kok = (kc + 8 <= kend);
    const int szk = kok ? 16 : 0;
    #pragma unroll
    for (int i = 0; i < 4; i++) {
        int row = lr + (i << 5);
        const __half* src = kok ? (A + (size_t)(m0 + row) * lda + kc) : A;
        uint32_t dst = smbase + p * 32768 + row * 128 + ((c16 ^ (row & 7)) << 4);
        cpasync16(dst, src, szk);
    }
    #pragma unroll
    for (int i = 0; i < 4; i++) {
        int row = lr + (i << 5);
        int n = n0 + row;
        bool ok = kok && (n < N);
        int sz = ok ? 16 : 0;
        const __half* src = ok ? (B + (size_t)n * ldb + kc) : B;
        uint32_t dst = smbase + p * 32768 + 16384 + row * 128 + ((c16 ^ (row & 7)) << 4);
        cpasync16(dst, src, sz);
    }
    CP_COMMIT();
}

__global__ void __launch_bounds__(256, 2) tmma2h(GDesc d0, GDesc d1)
{
    extern __shared__ __align__(1024) uint32_t sm[];
    const int tid = threadIdx.x;
    const int lane = tid & 31, wid = tid >> 5;
    const int wm = wid & 1, wn = wid >> 1;
    const int gid = lane >> 2, tg = lane & 3;

    int bx = blockIdx.x;
    const GDesc& d = (bx < d0.nCtas) ? d0 : d1;
    if (bx >= d0.nCtas) bx -= d0.nCtas;
    const int z = bx / d.ctasPerZ;
    const int r = bx % d.ctasPerZ;
    const int m0 = (r / d.ntiles) << 7;
    const int n0 = (r % d.ntiles) << 7;
    const int N = d.N, lda = d.lda, ldb = d.ldb, ldc = d.ldc;
    const __half* A = (const __half*)d.A;
    const __half* B = (const __half*)d.B;
    const int kstart = z * d.KC;
    int kend = kstart + d.KC; if (kend > d.K) kend = d.K;
    const int nb = (kend - kstart + 63) >> 6;

    const uint32_t smbase = smem_u32(sm);
    const int lr = tid >> 3, c16 = tid & 7;

    const int ahi = lane >> 4;
    const int bhi = (lane >> 3) & 1;
    uint32_t aoff[4]; int asw[4];
    #pragma unroll
    for (int mt = 0; mt < 4; mt++) {
        int rr = wm * 64 + mt * 16 + (lane & 15);
        aoff[mt] = rr * 128;
        asw[mt] = rr & 7;
    }
    uint32_t boff[2]; int bsw[2];
    #pragma unroll
    for (int nn = 0; nn < 2; nn++) {
        int rr = wn * 32 + nn * 16 + (lane & 7) + ((lane & 16) >> 1);
        boff[nn] = 16384 + rr * 128;
        bsw[nn] = rr & 7;
    }

    float c[4][4][4];
    #pragma unroll
    for (int i = 0; i < 4; i++)
        #pragma unroll
        for (int j = 0; j < 4; j++)
            #pragma unroll
            for (int q = 0; q < 4; q++) c[i][j][q] = 0.f;

    tmma_issue_h(smbase, 0, kstart, kend, A, lda, B, ldb, m0, n0, N, lr, c16);
    if (nb > 1)
        tmma_issue_h(smbase, 1, kstart + 64, kend, A, lda, B, ldb, m0, n0, N, lr, c16);
    else
        CP_COMMIT();

    for (int kb = 0; kb < nb; kb++) {
        CP_WAIT1();
        __syncthreads();
        const uint32_t sp = smbase + (kb % 3) * 32768;
        #pragma unroll
        for (int ks = 0; ks < 4; ks++) {
            uint32_t af[4][4], bf[4][2];
            #pragma unroll
            for (int mt = 0; mt < 4; mt++) {
                uint32_t ad = sp + aoff[mt] + ((((ks << 1) + ahi) ^ asw[mt]) << 4);
                LDSM4(af[mt][0], af[mt][1], af[mt][2], af[mt][3], ad);
            }
            #pragma unroll
            for (int nn = 0; nn < 2; nn++) {
                uint32_t r0, r1, r2, r3;
                uint32_t bd = sp + boff[nn] + ((((ks << 1) + bhi) ^ bsw[nn]) << 4);
                LDSM4(r0, r1, r2, r3, bd);
                bf[nn * 2][0] = r0; bf[nn * 2][1] = r1;
                bf[nn * 2 + 1][0] = r2; bf[nn * 2 + 1][1] = r3;
            }
            #pragma unroll
            for (int mt = 0; mt < 4; mt++)
                #pragma unroll
                for (int nt = 0; nt < 4; nt++)
                    mma_f16(c[mt][nt], af[mt], bf[nt]);
        }
        const int nk = kb + 2;
        if (nk < nb)
            tmma_issue_h(smbase, nk % 3, kstart + nk * 64, kend,
                         A, lda, B, ldb, m0, n0, N, lr, c16);
        else
            CP_COMMIT();
    }

    const float* bias = d.bias;
    float* Cz = d.C + (size_t)z * d.zstride;
    #pragma unroll
    for (int mt = 0; mt < 4; mt++) {
        int r0 = m0 + wm * 64 + mt * 16 + gid;
        #pragma unroll
        for (int nt = 0; nt < 4; nt++) {
            int cc = n0 + wn * 32 + nt * 8 + 2 * tg;
            float* p0 = Cz + (size_t)r0 * ldc + cc;
            float* p1 = p0 + 8 * ldc;
            if (cc < N) {
                float bb = bias ? bias[cc] : 0.f;
                p0[0] = c[mt][nt][0] + bb;
                p1[0] = c[mt][nt][2] + bb;
            }
            if (cc + 1 < N) {
                float bb = bias ? bias[cc + 1] : 0.f;
                p0[1] = c[mt][nt][1] + bb;
                p1[1] = c[mt][nt][3] + bb;
            }
        }
    }
}

// ================= prep: weight convert (5 segs) + embedding staging =================
struct ConvSegs {
    const float* src[5];
    __half* dst[5];
    int srcld[5], K[5], Kp[5];
    long start[6];
};

__global__ void prep_kernel(ConvSegs cs,
                            const int* __restrict__ input,
                            const int* __restrict__ input_d,
                            const float* __restrict__ hidden,
                            const float* __restrict__ ans,
                            const float* __restrict__ emb_w,
                            const float* __restrict__ emb_d_w,
                            float* __restrict__ aheadF,
                            __half* __restrict__ minpH)
{
    if (blockIdx.x < BB) {
        // ---- embed role ----
        int b = blockIdx.x, t = threadIdx.x;  // 256
        int tok = input[b];
        const float* src;
        if (tok > 2003) {
            int di = tok - 2004;
            if (di > LCC - 1) di = LCC - 1;
            if (di < 0) di = 0;
            int dt = input_d[b * LCC + di];
            src = emb_d_w + (size_t)dt * EE;
        } else {
            int tv = tok < 0 ? 0 : tok;
            src = emb_w + (size_t)tv * EE;
        }
        float* ah = aheadF + (size_t)b * AHEAD_K;
        __half* mp = minpH + (size_t)b * MINP_LD;
        for (int j = t; j < EE; j += 256) {
            float e = src[j];
            ah[512 + j] = e;
            mp[1536 + j] = __float2half_rn(e);
        }
        for (int h = t; h < HH; h += 256) {
            float hv = hidden[(size_t)b * HH + h];
            float av = ans[(size_t)b * HH + h];
            ah[h] = hv;
            ah[812 + h] = av;
            mp[1024 + h] = __float2half_rn(av);
        }
        if (t < 4) mp[1836 + t] = __float2half_rn(0.f);
    } else {
        // ---- weight convert role ----
        long total = cs.start[5] >> 3;
        long stride = 2048L * 256;
        for (long gidx = (long)(blockIdx.x - BB) * 256 + threadIdx.x;
             gidx < total; gidx += stride) {
            long e = gidx << 3;
            int s = 0;
            #pragma unroll
            for (int j = 0; j < 4; j++) if (e >= cs.start[j + 1]) s = j + 1;
            long loc = e - cs.start[s];
            int Kp = cs.Kp[s];
            long row = loc / Kp;
            int col = (int)(loc - row * Kp);
            const float* src = cs.src[s] + row * (long)cs.srcld[s] + col;
            int K = cs.K[s];
            __half2 h[4];
            if (col + 8 <= K) {
                float4 v0 = *(const float4*)src;
                float4 v1 = *(const float4*)(src + 4);
                h[0] = __floats2half2_rn(v0.x, v0.y);
                h[1] = __floats2half2_rn(v0.z, v0.w);
                h[2] = __floats2half2_rn(v1.x, v1.y);
                h[3] = __floats2half2_rn(v1.z, v1.w);
            } else {
                float tt[8];
                #pragma unroll
                for (int j = 0; j < 8; j++) tt[j] = (col + j < K) ? src[j] : 0.f;
                h[0] = __floats2half2_rn(tt[0], tt[1]);
                h[1] = __floats2half2_rn(tt[2], tt[3]);
                h[2] = __floats2half2_rn(tt[4], tt[5]);
                h[3] = __floats2half2_rn(tt[6], tt[7]);
            }
            *(uint4*)(cs.dst[s] + loc) = *(uint4*)h;
        }
    }
}

// ---------------- K3: partials reduce + tanh + softmax + fused c_t (fp16 annot) ----
__global__ void attn_finalize_ct(const float* __restrict__ partial,
                                 const float* __restrict__ attn_b,
                                 const __half* __restrict__ annotH,
                                 float* __restrict__ attnw,
                                 __half* __restrict__ minpH)
{
    __shared__ float pacc[512];
    __shared__ float sred[16];
    __shared__ float wsm[128];
    __shared__ float cacc[4096];
    int b = blockIdx.x, t = threadIdx.x;  // 512

    {
        int g = t >> 7, l = t & 127;
        const float* pb = partial + (size_t)b * (NSPLIT * LCC);
        float acc = 0.f;
        if (l < LCC) {
            int s0 = g * 17;
            #pragma unroll
            for (int s = 0; s < 17; s++) acc += pb[(s0 + s) * LCC + l];
        }
        pacc[t] = acc;
    }
    __syncthreads();
    float v = -1e30f;
    if (t < LCC)
        v = tanhf(attn_b[t] + pacc[t] + pacc[128 + t] + pacc[256 + t] + pacc[384 + t]);
    float m = warpReduceMax(v);
    if ((t & 31) == 0) sred[t >> 5] = m;
    __syncthreads();
    float mm = sred[0];
    #pragma unroll
    for (int w = 1; w < 16; w++) mm = fmaxf(mm, sred[w]);
    float e = (t < LCC) ? __expf(v - mm) : 0.f;
    float ss = warpReduceSum(e);
    __syncthreads();
    if ((t & 31) == 0) sred[t >> 5] = ss;
    __syncthreads();
    float tot = 0.f;
    #pragma unroll
    for (int w = 0; w < 16; w++) tot += sred[w];
    if (t < LCC) {
        float wv = e / tot;
        attnw[(size_t)b * LCC + t] = wv;
        wsm[t] = wv;
    }
    __syncthreads();

    // phase B: c_t[h] = sum_l w[l]*annot[b,l,h], fp16 reads, 8 l-groups x 64 h-chunks
    {
        int chunk = t & 63;       // 8 halfs -> h = chunk*8
        int g2 = t >> 6;          // 0..7
        const __half* Ab = annotH + (size_t)b * ANNOT_K + chunk * 8;
        float acc8[8];
        #pragma unroll
        for (int j = 0; j < 8; j++) acc8[j] = 0.f;
        int l = g2;
        for (; l + 8 < LCC; l += 16) {
            uint4 r0 = *(const uint4*)(Ab + (size_t)l * 512);
            uint4 r1 = *(const uint4*)(Ab + (size_t)(l + 8) * 512);
            float w0 = wsm[l], w1 = wsm[l + 8];
            const __half2* h0 = (const __half2*)&r0;
            const __half2* h1 = (const __half2*)&r1;
            #pragma unroll
            for (int j = 0; j < 4; j++) {
                float2 f0 = __half22float2(h0[j]);
                float2 f1 = __half22float2(h1[j]);
                acc8[2 * j]     = fmaf(w0, f0.x, fmaf(w1, f1.x, acc8[2 * j]));
                acc8[2 * j + 1] = fmaf(w0, f0.y, fmaf(w1, f1.y, acc8[2 * j + 1]));
            }
        }
        if (l < LCC) {
            uint4 r0 = *(const uint4*)(Ab + (size_t)l * 512);
            float w0 = wsm[l];
            const __half2* h0 = (const __half2*)&r0;
            #pragma unroll
            for (int j = 0; j < 4; j++) {
                float2 f0 = __half22float2(h0[j]);
                acc8[2 * j]     = fmaf(w0, f0.x, acc8[2 * j]);
                acc8[2 * j + 1] = fmaf(w0, f0.y, acc8[2 * j + 1]);
            }
        }
        #pragma unroll
        for (int j = 0; j < 8; j++) cacc[g2 * 512 + chunk * 8 + j] = acc8[j];
    }
    __syncthreads();
    {
        float s = 0.f;
        #pragma unroll
        for (int g = 0; g < 8; g++) s += cacc[g * 512 + t];
        minpH[(size_t)b * MINP_LD + 512 + t] = __float2half_rn(s);
    }
}

// ---------------- K5: GRU elementwise (3 gi partials + gh w/ bias) ----------------
__global__ void gru_kernel(const float* __restrict__ giP,
                           const float* __restrict__ gh,
                           const float* __restrict__ b_ih,
                           const float* __restrict__ h0,
                           __half* __restrict__ minpH,
                           float* __restrict__ out0,
                           float* __restrict__ out1)
{
    int i = blockIdx.x * blockDim.x + threadIdx.x;  // 512*512
    int b = i >> 9, h = i & 511;
    size_t o = (size_t)b * 1536;
    const float* g0 = giP + o;
    const float* g1 = giP + 786432 + o;
    const float* g2 = giP + 1572864 + o;
    const float* q = gh + o;
    float ir = g0[h] + g1[h] + g2[h] + b_ih[h];
    float iz = g0[512 + h] + g1[512 + h] + g2[512 + h] + b_ih[512 + h];
    float in_ = g0[1024 + h] + g1[1024 + h] + g2[1024 + h] + b_ih[1024 + h];
    float hr = q[h];
    float hz = q[512 + h];
    float hn = q[1024 + h];
    float r = 1.f / (1.f + __expf(-(ir + hr)));
    float z = 1.f / (1.f + __expf(-(iz + hz)));
    float n = tanhf(in_ + r * hn);
    float hnew = (1.f - z) * n + z * h0[i];
    minpH[(size_t)b * MINP_LD + h] = __float2half_rn(hnew);
    out0[i] = hnew;
    out1[i] = hnew;
}

// ---------------- fused combine (et: 8 parts | z1: 4 parts + tanh), fp16 out -------
__global__ void combine2(const float* __restrict__ pa, const float* __restrict__ ba,
                         __half* __restrict__ oa,
                         const float* __restrict__ pz, const float* __restrict__ bz,
                         __half* __restrict__ oz)
{
    int blk = blockIdx.x;
    if (blk < 1024) {
        int i = blk * 256 + threadIdx.x;
        float v = ba[i & 511];
        #pragma unroll
        for (int j = 0; j < 8; j++) v += pa[i + (size_t)j * 262144];
        oa[i] = __float2half_rn(v);
    } else {
        int i = (blk - 1024) * 256 + threadIdx.x;
        float v = bz[i & 1023];
        #pragma unroll
        for (int j = 0; j < 4; j++) v += pz[i + (size_t)j * 524288];
        oz[i] = __float2half_rn(tanhf(v));
    }
}

// ---------------- K6: olog combine + z2/z_t + softmax + log -> p_t ----------------
__global__ void final_kernel(const float* __restrict__ ologP,
                             const float* __restrict__ out_b,
                             const float* __restrict__ z2P,
                             const float* __restrict__ zt_b2,
                             const float* __restrict__ zt_W3,
                             const float* __restrict__ zt_b3,
                             const float* __restrict__ attnw,
                             float* __restrict__ pout)
{
    __shared__ float buf[OO];
    __shared__ float sred[16];
    __shared__ float sbc;
    int b = blockIdx.x, t = threadIdx.x;  // 512 threads

    size_t o = (size_t)b * HH + t;
    float zv = z2P[o] + z2P[262144 + o] + z2P[524288 + o] + z2P[786432 + o] + zt_b2[t];
    zv = tanhf(zv);
    float s = zv * zt_W3[t];
    s = warpReduceSum(s);
    if ((t & 31) == 0) sred[t >> 5] = s;
    __syncthreads();
    if (t == 0) {
        float tot = 0.f;
        for (int w = 0; w < 16; w++) tot += sred[w];
        sbc = 1.f / (1.f + __expf(-(tot + zt_b3[0])));
    }
    __syncthreads();
    float zt = sbc;

    const float* ob0 = ologP + (size_t)b * OO;
    const float* ob1 = ob0 + (size_t)BB * OO;
    float mx = -1e30f;
    for (int j = t; j < OO; j += 512) {
        float v = ob0[j] + ob1[j] + out_b[j];
        buf[j] = v;
        mx = fmaxf(mx, v);
    }
    mx = warpReduceMax(mx);
    __syncthreads();
    if ((t & 31) == 0) sred[t >> 5] = mx;
    __syncthreads();
    if (t == 0) {
        float m2 = sred[0];
        for (int w = 1; w < 16; w++) m2 = fmaxf(m2, sred[w]);
        sbc = m2;
    }
    __syncthreads();
    mx = sbc;

    float se = 0.f;
    for (int j = t; j < OO; j += 512) {
        float e = __expf(buf[j] - mx);
        buf[j] = e;
        se += e;
    }
    se = warpReduceSum(se);
    __syncthreads();
    if ((t & 31) == 0) sred[t >> 5] = se;
    __syncthreads();
    if (t == 0) {
        float tot = 0.f;
        for (int w = 0; w < 16; w++) tot += sred[w];
        sbc = tot;
    }
    __syncthreads();
    float cc = zt / sbc;

    float* pb = pout + (size_t)b * (OO + LCC);
    for (int j = t; j < OO; j += 512)
        pb[j] = __logf(buf[j] * cc + 1e-20f);
    float omz = 1.f - zt;
    for (int l = t; l < LCC; l += 512)
        pb[OO + l] = __logf(attnw[(size_t)b * LCC + l] * omz + 1e-20f);
}

// ---------------- launch ----------------
static GDesc mkdesc(const void* A, int lda, const void* B, int ldb,
                    const float* bias, float* C, int ldc,
                    int M, int N, int K, int KC, long zstride, int zcount,
                    __half* sideout = nullptr)
{
    GDesc d;
    d.A = A; d.B = B; d.bias = bias; d.C = C; d.sideout = sideout;
    d.lda = lda; d.ldb = ldb; d.ldc = ldc;
    d.N = N; d.K = K; d.KC = KC; d.zstride = zstride;
    d.ntiles = (N + 127) / 128;
    d.ctasPerZ = (M / 128) * d.ntiles;
    d.nCtas = d.ctasPerZ * zcount;
    return d;
}

extern "C" void kernel_launch(void* const* d_in, const int* in_sizes, int n_in,
                              void* d_out, int out_size)
{
    const int*   input   = (const int*)d_in[0];
    const int*   input_d = (const int*)d_in[1];
    const float* hidden  = (const float*)d_in[2];
    const float* annot   = (const float*)d_in[3];
    const float* ans     = (const float*)d_in[4];
    const float* emb_w   = (const float*)d_in[5];
    const float* emb_d_w = (const float*)d_in[6];
    const float* attn_W  = (const float*)d_in[7];
    const float* attn_b  = (const float*)d_in[8];
    const float* W_ih    = (const float*)d_in[9];
    const float* W_hh    = (const float*)d_in[10];
    const float* b_ih    = (const float*)d_in[11];
    const float* b_hh    = (const float*)d_in[12];
    const float* mlp_W   = (const float*)d_in[13];
    const float* mlp_b   = (const float*)d_in[14];
    const float* out_W   = (const float*)d_in[15];
    const float* out_b   = (const float*)d_in[16];
    const float* zt_W1   = (const float*)d_in[17];
    const float* zt_b1   = (const float*)d_in[18];
    const float* zt_W2   = (const float*)d_in[19];
    const float* zt_b2   = (const float*)d_in[20];
    const float* zt_W3   = (const float*)d_in[21];
    const float* zt_b3   = (const float*)d_in[22];
    float* out = (float*)d_out;

    float* f32 = nullptr;  __half* f16 = nullptr;
    cudaGetSymbolAddress((void**)&f32, g_f32);
    cudaGetSymbolAddress((void**)&f16, g_f16);

    float* part   = f32 + OFF_PART;
    float* attnw  = f32 + OFF_ATTNW;
    float* giP    = f32 + OFF_GIP;
    float* gh     = f32 + OFF_GH;
    float* etP    = f32 + OFF_ETP;
    float* ologP  = f32 + OFF_OLOGP;
    float* z1P    = f32 + OFF_Z1P;
    float* z2P    = f32 + OFF_Z2P;
    float* aheadF = f32 + OFF_AHEAD;

    __half* annotH = f16 + HOFF_ANNOT;
    __half* WihH   = f16 + HOFF_WIH;
    __half* mlpWH  = f16 + HOFF_MLPW;
    __half* outWH  = f16 + HOFF_OUTW;
    __half* z1WH   = f16 + HOFF_Z1W;
    __half* z2WH   = f16 + HOFF_Z2W;
    __half* minpH  = f16 + HOFF_MINP;
    __half* etH    = f16 + HOFF_ET;
    __half* z1H    = f16 + HOFF_Z1;

    cudaFuncSetAttribute(tmma3f, cudaFuncAttributeMaxDynamicSharedMemorySize, TMMA_SMEM);
    cudaFuncSetAttribute(tmma2h, cudaFuncAttributeMaxDynamicSharedMemorySize, TMMA_SMEM);

    // 0. prep: weight convert + embedding staging (one launch)
    ConvSegs cs;
    const float* srcs[5] = {W_ih, mlp_W, out_W, zt_W1, zt_W2};
    __half* dsts[5] = {WihH, mlpWH, outWH, z1WH, z2WH};
    int slds[5] = {1324, 1836, 512, 1836, 1024};
    int Ks[5]   = {1324, 1836, 512, 1836, 1024};
    int Kps[5]  = {1328, 1840, 512, 1840, 1024};
    long rows[5] = {1536, 512, 2004, 1024, 512};
    long acc = 0;
    for (int i = 0; i < 5; i++) {
        cs.src[i] = srcs[i]; cs.dst[i] = dsts[i];
        cs.srcld[i] = slds[i]; cs.K[i] = Ks[i]; cs.Kp[i] = Kps[i];
        cs.start[i] = acc;
        acc += rows[i] * Kps[i];
    }
    cs.start[5] = acc;
    prep_kernel<<<BB + 2048, 256>>>(cs, input, input_d, hidden, ans,
                                    emb_w, emb_d_w, aheadF, minpH);

    // 2. tf32 triple: attn-annot (z=64, writes annotH) + attn-head (z=4) + gh
    GDesc dAA = mkdesc(annot, ANNOT_K, attn_W + AHEAD_K, 52524, nullptr,
                       part, NSPLIT * LCC, BB, LCC, ANNOT_K, 800, LCC, 64, annotH);
    GDesc dAH = mkdesc(aheadF, AHEAD_K, attn_W, 52524, nullptr,
                       part + 64 * LCC, NSPLIT * LCC, BB, LCC, AHEAD_K, 332, LCC, 4);
    GDesc dGH = mkdesc(hidden, HH, W_hh, HH, b_hh,
                       gh, 1536, BB, 1536, HH, HH, 0, 1);
    tmma3f<<<dAA.nCtas + dAH.nCtas + dGH.nCtas, 256, TMMA_SMEM>>>(dAA, dAH, dGH);

    // 3. finalize + fused c_t (reads fp16 annotH)
    attn_finalize_ct<<<BB, 512>>>(part, attn_b, annotH, attnw, minpH);

    // 4. gi (fp16, z=3), then GRU elementwise
    GDesc dGI = mkdesc(minpH + 512, MINP_LD, WihH, WIH_LD, nullptr,
                       giP, 1536, BB, 1536, WIH_LD, 448, 786432, 3);
    tmma2h<<<dGI.nCtas, 256, TMMA_SMEM>>>(dGI, dGI);
    gru_kernel<<<1024, 256>>>(giP, gh, b_ih, hidden, minpH, out, out + BB * HH);

    // 5. mlp + z1 fused, then fused combine
    GDesc dML = mkdesc(minpH, MINP_LD, mlpWH, MINP_LD, nullptr,
                       etP, HH, BB, HH, MINP_LD, 232, 262144, 8);
    GDesc dZ1 = mkdesc(minpH, MINP_LD, z1WH, MINP_LD, nullptr,
                       z1P, 1024, BB, 1024, MINP_LD, 464, 524288, 4);
    tmma2h<<<dML.nCtas + dZ1.nCtas, 256, TMMA_SMEM>>>(dML, dZ1);
    combine2<<<3072, 256>>>(etP, mlp_b, etH, z1P, zt_b1, z1H);

    // 6. output head (z=2, bias deferred) + z2 fused
    GDesc dOU = mkdesc(etH, HH, outWH, HH, nullptr,
                       ologP, OO, BB, OO, HH, 256, (long)BB * OO, 2);
    GDesc dZ2 = mkdesc(z1H, 1024, z2WH, 1024, nullptr,
                       z2P, HH, BB, HH, 1024, 256, 262144, 4);
    tmma2h<<<dOU.nCtas + dZ2.nCtas, 256, TMMA_SMEM>>>(dOU, dZ2);

    // 7. final: olog combine + z_t + softmax/log + p_t
    final_kernel<<<BB, 512>>>(ologP, out_b, z2P, zt_b2, zt_W3, zt_b3, attnw,
                              out + 2 * BB * HH);
}